// round 8
// baseline (speedup 1.0000x reference)
#include <cuda_runtime.h>
#include <cuda_fp16.h>
#include <cstddef>

#define N_USERS 50000
#define N_ENT   100000
#define N_TOT   150000
#define D       64
#define E_CAP   1536000

// ---------------------------------------------------------------------------
// Scratch (device globals: no allocation allowed)
// ---------------------------------------------------------------------------
__device__ __align__(256) __half g_yh[(size_t)N_TOT * D];
__device__ float g_Z;                 // zeroed by scan_final before edge pass
__device__ int g_deg[N_TOT];          // zeroed statically + by finalize (prev run)
__device__ int g_off[N_TOT + 1];
__device__ int g_cur[N_TOT];
__device__ int g_src_sorted[E_CAP];
__device__ int g_part[1024];

static const int NB_SCAN = (N_TOT + 255) / 256;   // 586

// ---------------------------------------------------------------------------
// build branch: y = x @ W (fp32 math, fp16 store). Tile = 128 rows.
// ---------------------------------------------------------------------------
__global__ void __launch_bounds__(256) build_y_kernel(
    const int* __restrict__ uidx, const int* __restrict__ iidx,
    const float* __restrict__ ut, const float* __restrict__ et,
    const float* __restrict__ W)
{
    __shared__ float Ws[64 * 64];
    __shared__ float xst[64][128];

    const int tid = threadIdx.x;
    for (int i = tid; i < 1024; i += 256)
        ((float4*)Ws)[i] = ((const float4*)W)[i];

    const int row0 = blockIdx.x * 128;
    {
        const int lr = tid >> 1;
        const int lj = tid & 1;
        const int r  = row0 + lr;
        if (r < N_TOT) {
            const float* xrow;
            if (r < N_USERS) xrow = ut + (size_t)__ldg(uidx + r) * D;
            else             xrow = et + (size_t)__ldg(iidx + (r - N_USERS)) * D;
            #pragma unroll
            for (int i = 0; i < 8; i++) {
                const int c4 = lj * 8 + i;
                float4 v = ((const float4*)xrow)[c4];
                xst[c4 * 4 + 0][lr] = v.x;
                xst[c4 * 4 + 1][lr] = v.y;
                xst[c4 * 4 + 2][lr] = v.z;
                xst[c4 * 4 + 3][lr] = v.w;
            }
        }
    }
    __syncthreads();

    const int j  = tid & 15;
    const int rt = tid >> 4;

    float4 acc[8];
    #pragma unroll
    for (int r = 0; r < 8; r++) acc[r] = make_float4(0.f, 0.f, 0.f, 0.f);

    #pragma unroll 4
    for (int k = 0; k < 64; k++) {
        const float4 w  = *(const float4*)&Ws[k * 64 + j * 4];
        const float4 xa = *(const float4*)&xst[k][rt * 8];
        const float4 xb = *(const float4*)&xst[k][rt * 8 + 4];
        acc[0].x += xa.x * w.x; acc[0].y += xa.x * w.y; acc[0].z += xa.x * w.z; acc[0].w += xa.x * w.w;
        acc[1].x += xa.y * w.x; acc[1].y += xa.y * w.y; acc[1].z += xa.y * w.z; acc[1].w += xa.y * w.w;
        acc[2].x += xa.z * w.x; acc[2].y += xa.z * w.y; acc[2].z += xa.z * w.z; acc[2].w += xa.z * w.w;
        acc[3].x += xa.w * w.x; acc[3].y += xa.w * w.y; acc[3].z += xa.w * w.z; acc[3].w += xa.w * w.w;
        acc[4].x += xb.x * w.x; acc[4].y += xb.x * w.y; acc[4].z += xb.x * w.z; acc[4].w += xb.x * w.w;
        acc[5].x += xb.y * w.x; acc[5].y += xb.y * w.y; acc[5].z += xb.y * w.z; acc[5].w += xb.y * w.w;
        acc[6].x += xb.z * w.x; acc[6].y += xb.z * w.y; acc[6].z += xb.z * w.z; acc[6].w += xb.z * w.w;
        acc[7].x += xb.w * w.x; acc[7].y += xb.w * w.y; acc[7].z += xb.w * w.z; acc[7].w += xb.w * w.w;
    }

    #pragma unroll
    for (int r = 0; r < 8; r++) {
        const int row = row0 + rt * 8 + r;
        if (row < N_TOT) {
            __half2 h0 = __floats2half2_rn(acc[r].x, acc[r].y);
            __half2 h1 = __floats2half2_rn(acc[r].z, acc[r].w);
            uint2 u = make_uint2(*(unsigned*)&h0, *(unsigned*)&h1);
            ((uint2*)(g_yh + (size_t)row * D))[j] = u;
        }
    }
}

// ---------------------------------------------------------------------------
// Counting sort by dst. g_deg arrives zeroed (static init / previous finalize).
// ---------------------------------------------------------------------------
__global__ void hist_kernel(const int* __restrict__ ei, int E) {
    const int n4 = E >> 2;
    const int st = gridDim.x * blockDim.x;
    const int4* d4 = (const int4*)(ei + E);
    for (int i = blockIdx.x * blockDim.x + threadIdx.x; i < n4; i += st) {
        int4 d = __ldg(d4 + i);
        atomicAdd(&g_deg[d.x], 1); atomicAdd(&g_deg[d.y], 1);
        atomicAdd(&g_deg[d.z], 1); atomicAdd(&g_deg[d.w], 1);
    }
    for (int e = (n4 << 2) + blockIdx.x * blockDim.x + threadIdx.x; e < E; e += st)
        atomicAdd(&g_deg[__ldg(ei + E + e)], 1);
}

__global__ void __launch_bounds__(256) scan_reduce_kernel() {
    const int t = threadIdx.x;
    const int idx = blockIdx.x * 256 + t;
    int v = (idx < N_TOT) ? g_deg[idx] : 0;
    #pragma unroll
    for (int o = 16; o > 0; o >>= 1) v += __shfl_xor_sync(0xffffffffu, v, o);
    __shared__ int sw[8];
    if ((t & 31) == 0) sw[t >> 5] = v;
    __syncthreads();
    if (t == 0) {
        int s = 0;
        #pragma unroll
        for (int w = 0; w < 8; w++) s += sw[w];
        g_part[blockIdx.x] = s;
    }
}

__global__ void __launch_bounds__(256) scan_final_kernel(int nb) {
    __shared__ int s[256];
    __shared__ int sbase;
    const int t = threadIdx.x;
    const int b = blockIdx.x;

    if (b == 0 && t == 0) g_Z = 0.0f;   // reset for this run's edge pass

    int acc = 0;
    for (int j = t; j < b; j += 256) acc += g_part[j];
    #pragma unroll
    for (int o = 16; o > 0; o >>= 1) acc += __shfl_xor_sync(0xffffffffu, acc, o);
    __shared__ int sw[8];
    if ((t & 31) == 0) sw[t >> 5] = acc;
    __syncthreads();
    if (t == 0) {
        int ss = 0;
        #pragma unroll
        for (int w = 0; w < 8; w++) ss += sw[w];
        sbase = ss;
    }

    const int idx = b * 256 + t;
    int v = (idx < N_TOT) ? g_deg[idx] : 0;
    s[t] = v; __syncthreads();
    #pragma unroll
    for (int o = 1; o < 256; o <<= 1) {
        int x = (t >= o) ? s[t - o] : 0;
        __syncthreads();
        s[t] += x;
        __syncthreads();
    }
    const int off = sbase + s[t] - v;
    if (idx < N_TOT) {
        g_off[idx] = off;
        g_cur[idx] = off;
        if (idx == N_TOT - 1) g_off[N_TOT] = off + v;
    }
}

__global__ void scatter_kernel(const int* __restrict__ ei, int E) {
    const int n4 = E >> 2;
    const int st = gridDim.x * blockDim.x;
    const int4* s4p = (const int4*)ei;
    const int4* d4p = (const int4*)(ei + E);
    for (int i = blockIdx.x * blockDim.x + threadIdx.x; i < n4; i += st) {
        int4 sv = __ldg(s4p + i);
        int4 dv = __ldg(d4p + i);
        g_src_sorted[atomicAdd(&g_cur[dv.x], 1)] = sv.x;
        g_src_sorted[atomicAdd(&g_cur[dv.y], 1)] = sv.y;
        g_src_sorted[atomicAdd(&g_cur[dv.z], 1)] = sv.z;
        g_src_sorted[atomicAdd(&g_cur[dv.w], 1)] = sv.w;
    }
    for (int e = (n4 << 2) + blockIdx.x * blockDim.x + threadIdx.x; e < E; e += st) {
        const int d = __ldg(ei + E + e);
        g_src_sorted[atomicAdd(&g_cur[d], 1)] = __ldg(ei + e);
    }
}

// ---------------------------------------------------------------------------
// Edge pass (CSR): one warp per dst, halves = edge pairs of the SAME node.
// LATENCY FIX: (a) all edge indices of a node fetched in ONE coalesced LDG,
// per-iter index via register shuffle; (b) next row gather issued before the
// current iteration's compute (software pipeline). deg>32 -> uniform fallback.
// ---------------------------------------------------------------------------
__global__ void __launch_bounds__(256) edge_csr_kernel(float* __restrict__ out)
{
    const int lane = threadIdx.x & 31;
    const int li   = lane & 15;
    const int half = lane >> 4;
    const int wid  = (blockIdx.x * blockDim.x + threadIdx.x) >> 5;
    const int nw   = (gridDim.x * blockDim.x) >> 5;

    float zloc = 0.0f;

    for (int d = wid; d < N_TOT; d += nw) {
        float2 yd0, yd1;
        {
            uint2 u = __ldg((const uint2*)(g_yh + (size_t)d * D) + li);
            yd0 = __half22float2(*(__half2*)&u.x);
            yd1 = __half22float2(*(__half2*)&u.y);
        }
        const int beg = __ldg(&g_off[d]);
        const int end = __ldg(&g_off[d + 1]);
        const int deg = end - beg;

        float4 acc = make_float4(0.f, 0.f, 0.f, 0.f);

        if (deg > 0 && deg <= 32) {
            // one coalesced load of ALL this node's edge indices
            const int s_all = __ldg(g_src_sorted + beg + min(lane, deg - 1));
            const int npairs = (deg + 1) >> 1;

            // prologue: row for iter 0
            int s_c = __shfl_sync(0xffffffffu, s_all, min(half, deg - 1));
            uint2 u_c = __ldg((const uint2*)(g_yh + (size_t)s_c * D) + li);

            for (int it = 0; it < npairs; it++) {
                // prefetch next iteration's row (clamped duplicate on tail)
                const int nsrc = min(2 * (it + 1) + half, deg - 1);
                const int s_n = __shfl_sync(0xffffffffu, s_all, nsrc);
                uint2 u_n = __ldg((const uint2*)(g_yh + (size_t)s_n * D) + li);

                float2 a0 = __half22float2(*(__half2*)&u_c.x);
                float2 a1 = __half22float2(*(__half2*)&u_c.y);
                float t = a0.x * yd0.x + a0.y * yd0.y + a1.x * yd1.x + a1.y * yd1.y;
                t += __shfl_xor_sync(0xffffffffu, t, 8);
                t += __shfl_xor_sync(0xffffffffu, t, 4);
                t += __shfl_xor_sync(0xffffffffu, t, 2);
                t += __shfl_xor_sync(0xffffffffu, t, 1);

                float p = __expf(t >= 0.f ? t : 0.2f * t);
                p = (2 * it + half < deg) ? p : 0.f;

                if (li == 0) zloc += p;
                acc.x += p * a0.x; acc.y += p * a0.y;
                acc.z += p * a1.x; acc.w += p * a1.y;
                u_c = u_n;
            }
        } else if (deg > 32) {
            // rare fallback (warp-uniform), non-pipelined
            const int npairs = (deg + 1) >> 1;
            for (int it = 0; it < npairs; it++) {
                const int i = beg + 2 * it + half;
                const bool valid = (i < end);
                const int i2 = valid ? i : (end - 1);
                const int s = __ldg(g_src_sorted + i2);
                uint2 u = __ldg((const uint2*)(g_yh + (size_t)s * D) + li);
                float2 a0 = __half22float2(*(__half2*)&u.x);
                float2 a1 = __half22float2(*(__half2*)&u.y);
                float t = a0.x * yd0.x + a0.y * yd0.y + a1.x * yd1.x + a1.y * yd1.y;
                t += __shfl_xor_sync(0xffffffffu, t, 8);
                t += __shfl_xor_sync(0xffffffffu, t, 4);
                t += __shfl_xor_sync(0xffffffffu, t, 2);
                t += __shfl_xor_sync(0xffffffffu, t, 1);
                float p = __expf(t >= 0.f ? t : 0.2f * t);
                p = valid ? p : 0.f;
                if (li == 0) zloc += p;
                acc.x += p * a0.x; acc.y += p * a0.y;
                acc.z += p * a1.x; acc.w += p * a1.y;
            }
        }

        // merge halves
        acc.x += __shfl_xor_sync(0xffffffffu, acc.x, 16);
        acc.y += __shfl_xor_sync(0xffffffffu, acc.y, 16);
        acc.z += __shfl_xor_sync(0xffffffffu, acc.z, 16);
        acc.w += __shfl_xor_sync(0xffffffffu, acc.w, 16);
        if (half == 0)
            *(float4*)(out + (size_t)d * D + li * 4) = acc;
    }

    float z = zloc;
    #pragma unroll
    for (int o = 16; o > 0; o >>= 1) z += __shfl_xor_sync(0xffffffffu, z, o);
    __shared__ float sz[8];
    if (lane == 0) sz[threadIdx.x >> 5] = z;
    __syncthreads();
    if (threadIdx.x == 0) {
        float s = 0.f;
        #pragma unroll
        for (int w = 0; w < 8; w++) s += sz[w];
        atomicAdd(&g_Z, s);
    }
}

// ---------------------------------------------------------------------------
// finalize: out = relu(out)/Z, and re-zero g_deg for the NEXT run.
// ---------------------------------------------------------------------------
__global__ void __launch_bounds__(256) finalize_kernel(float* __restrict__ out, int n)
{
    const float invZ = 1.0f / g_Z;
    const int n4 = n >> 2;
    float4* o4 = (float4*)out;
    const int st = gridDim.x * blockDim.x;
    for (int i = blockIdx.x * blockDim.x + threadIdx.x; i < n4; i += st) {
        float4 v = o4[i];
        v.x = v.x > 0.f ? v.x * invZ : 0.f;
        v.y = v.y > 0.f ? v.y * invZ : 0.f;
        v.z = v.z > 0.f ? v.z * invZ : 0.f;
        v.w = v.w > 0.f ? v.w * invZ : 0.f;
        o4[i] = v;
    }
    // prepare histogram for next invocation (graph replays are sequential)
    int4 z4 = make_int4(0, 0, 0, 0);
    for (int i = blockIdx.x * blockDim.x + threadIdx.x; i < N_TOT / 4; i += st)
        ((int4*)g_deg)[i] = z4;
}

// ---------------------------------------------------------------------------
// Launch: fork-join — sort chain (s2) overlaps build_y (stream 0).
// ---------------------------------------------------------------------------
extern "C" void kernel_launch(void* const* d_in, const int* in_sizes, int n_in,
                              void* d_out, int out_size)
{
    const int*   uidx = (const int*)d_in[0];
    const int*   iidx = (const int*)d_in[1];
    const int*   ei   = (const int*)d_in[2];
    const float* ut   = (const float*)d_in[5];
    const float* et   = (const float*)d_in[6];
    const float* W    = (const float*)d_in[7];
    float* out = (float*)d_out;
    const int E = in_sizes[2] / 2;

    static cudaStream_t s2 = nullptr;
    static cudaEvent_t ev_fork = nullptr, ev_join = nullptr;
    if (s2 == nullptr) {
        cudaStreamCreateWithFlags(&s2, cudaStreamNonBlocking);
        cudaEventCreateWithFlags(&ev_fork, cudaEventDisableTiming);
        cudaEventCreateWithFlags(&ev_join, cudaEventDisableTiming);
    }

    cudaEventRecord(ev_fork, 0);
    cudaStreamWaitEvent(s2, ev_fork, 0);
    hist_kernel<<<592, 256, 0, s2>>>(ei, E);
    scan_reduce_kernel<<<NB_SCAN, 256, 0, s2>>>();
    scan_final_kernel<<<NB_SCAN, 256, 0, s2>>>(NB_SCAN);
    scatter_kernel<<<592, 256, 0, s2>>>(ei, E);
    cudaEventRecord(ev_join, s2);

    build_y_kernel<<<(N_TOT + 127) / 128, 256>>>(uidx, iidx, ut, et, W);

    cudaStreamWaitEvent(0, ev_join, 0);
    edge_csr_kernel<<<1184, 256>>>(out);
    finalize_kernel<<<1184, 256>>>(out, out_size);
}

// round 9
// speedup vs baseline: 1.1014x; 1.1014x over previous
#include <cuda_runtime.h>
#include <cuda_fp16.h>
#include <cstddef>

#define N_USERS 50000
#define N_ENT   100000
#define N_TOT   150000
#define D       64

// ---------------------------------------------------------------------------
// Scratch: y = x @ W in fp16 (sole consumer: edge pass), softmax denominator.
// ---------------------------------------------------------------------------
__device__ __align__(256) __half g_yh[(size_t)N_TOT * D];
__device__ float g_Z;

// ---------------------------------------------------------------------------
// init Z (tiny, runs on side stream with the memset)
// ---------------------------------------------------------------------------
__global__ void init_z_kernel() { g_Z = 0.0f; }

// ---------------------------------------------------------------------------
// build: y = x @ W (fp32 math, fp16 store). Tile = 128 rows, 256 threads.
// ---------------------------------------------------------------------------
__global__ void __launch_bounds__(256) build_y_kernel(
    const int* __restrict__ uidx, const int* __restrict__ iidx,
    const float* __restrict__ ut, const float* __restrict__ et,
    const float* __restrict__ W)
{
    __shared__ float Ws[64 * 64];
    __shared__ float xst[64][128];

    const int tid = threadIdx.x;
    for (int i = tid; i < 1024; i += 256)
        ((float4*)Ws)[i] = ((const float4*)W)[i];

    const int row0 = blockIdx.x * 128;
    {
        const int lr = tid >> 1;
        const int lj = tid & 1;
        const int r  = row0 + lr;
        if (r < N_TOT) {
            const float* xrow;
            if (r < N_USERS) xrow = ut + (size_t)__ldg(uidx + r) * D;
            else             xrow = et + (size_t)__ldg(iidx + (r - N_USERS)) * D;
            #pragma unroll
            for (int i = 0; i < 8; i++) {
                const int c4 = lj * 8 + i;
                float4 v = ((const float4*)xrow)[c4];
                xst[c4 * 4 + 0][lr] = v.x;
                xst[c4 * 4 + 1][lr] = v.y;
                xst[c4 * 4 + 2][lr] = v.z;
                xst[c4 * 4 + 3][lr] = v.w;
            }
        }
    }
    __syncthreads();

    const int j  = tid & 15;
    const int rt = tid >> 4;

    float4 acc[8];
    #pragma unroll
    for (int r = 0; r < 8; r++) acc[r] = make_float4(0.f, 0.f, 0.f, 0.f);

    #pragma unroll 4
    for (int k = 0; k < 64; k++) {
        const float4 w  = *(const float4*)&Ws[k * 64 + j * 4];
        const float4 xa = *(const float4*)&xst[k][rt * 8];
        const float4 xb = *(const float4*)&xst[k][rt * 8 + 4];
        acc[0].x += xa.x * w.x; acc[0].y += xa.x * w.y; acc[0].z += xa.x * w.z; acc[0].w += xa.x * w.w;
        acc[1].x += xa.y * w.x; acc[1].y += xa.y * w.y; acc[1].z += xa.y * w.z; acc[1].w += xa.y * w.w;
        acc[2].x += xa.z * w.x; acc[2].y += xa.z * w.y; acc[2].z += xa.z * w.z; acc[2].w += xa.z * w.w;
        acc[3].x += xa.w * w.x; acc[3].y += xa.w * w.y; acc[3].z += xa.w * w.z; acc[3].w += xa.w * w.w;
        acc[4].x += xb.x * w.x; acc[4].y += xb.x * w.y; acc[4].z += xb.x * w.z; acc[4].w += xb.x * w.w;
        acc[5].x += xb.y * w.x; acc[5].y += xb.y * w.y; acc[5].z += xb.y * w.z; acc[5].w += xb.y * w.w;
        acc[6].x += xb.z * w.x; acc[6].y += xb.z * w.y; acc[6].z += xb.z * w.z; acc[6].w += xb.z * w.w;
        acc[7].x += xb.w * w.x; acc[7].y += xb.w * w.y; acc[7].z += xb.w * w.z; acc[7].w += xb.w * w.w;
    }

    #pragma unroll
    for (int r = 0; r < 8; r++) {
        const int row = row0 + rt * 8 + r;
        if (row < N_TOT) {
            __half2 h0 = __floats2half2_rn(acc[r].x, acc[r].y);
            __half2 h1 = __floats2half2_rn(acc[r].z, acc[r].w);
            uint2 u = make_uint2(*(unsigned*)&h0, *(unsigned*)&h1);
            ((uint2*)(g_yh + (size_t)row * D))[j] = u;
        }
    }
}

// ---------------------------------------------------------------------------
// Fused edge pass (NO SORT): per edge -> gather both fp16 rows, dot (4 shuffles
// within 16-lane half), exp, vectorized red.global into out[dst], Z accumulate.
// 16-lane group per edge; per-half shuffle masks (halves may diverge by 1 iter).
// ---------------------------------------------------------------------------
__global__ void __launch_bounds__(256) edge_kernel(
    const int* __restrict__ ei, int E, float* __restrict__ out)
{
    const int lane = threadIdx.x & 31;
    const int li   = lane & 15;
    const unsigned mask = 0xFFFFu << ((lane >> 4) * 16);
    const int gid  = (blockIdx.x * blockDim.x + threadIdx.x) >> 4;
    const int ng   = (gridDim.x * blockDim.x) >> 4;

    float zloc = 0.0f;

    for (int e = gid; e < E; e += ng) {
        const int src = __ldg(ei + e);
        const int dst = __ldg(ei + E + e);

        uint2 us = __ldg((const uint2*)(g_yh + (size_t)src * D) + li);
        uint2 ud = __ldg((const uint2*)(g_yh + (size_t)dst * D) + li);
        float2 s0 = __half22float2(*(__half2*)&us.x);
        float2 s1 = __half22float2(*(__half2*)&us.y);
        float2 d0 = __half22float2(*(__half2*)&ud.x);
        float2 d1 = __half22float2(*(__half2*)&ud.y);

        float t = s0.x * d0.x + s0.y * d0.y + s1.x * d1.x + s1.y * d1.y;
        t += __shfl_xor_sync(mask, t, 8);
        t += __shfl_xor_sync(mask, t, 4);
        t += __shfl_xor_sync(mask, t, 2);
        t += __shfl_xor_sync(mask, t, 1);

        const float p = __expf(t >= 0.f ? t : 0.2f * t);   // leaky_relu(0.2)
        if (li == 0) zloc += p;

        float* dp = out + (size_t)dst * D + li * 4;
        asm volatile("red.global.add.v4.f32 [%0], {%1,%2,%3,%4};"
                     :: "l"(dp), "f"(p * s0.x), "f"(p * s0.y),
                        "f"(p * s1.x), "f"(p * s1.y)
                     : "memory");
    }

    // block-reduce zloc -> one atomic per block (loop done; full mask safe)
    float z = zloc;
    #pragma unroll
    for (int o = 16; o > 0; o >>= 1) z += __shfl_xor_sync(0xffffffffu, z, o);
    __shared__ float sz[8];
    if (lane == 0) sz[threadIdx.x >> 5] = z;
    __syncthreads();
    if (threadIdx.x == 0) {
        float s = 0.f;
        #pragma unroll
        for (int w = 0; w < 8; w++) s += sz[w];
        atomicAdd(&g_Z, s);
    }
}

// ---------------------------------------------------------------------------
// finalize: out = relu(out) / Z   (relu(a/Z) == relu(a)/Z since Z > 0)
// ---------------------------------------------------------------------------
__global__ void __launch_bounds__(256) finalize_kernel(float* __restrict__ out, int n)
{
    const float invZ = 1.0f / g_Z;
    const int n4 = n >> 2;
    float4* o4 = (float4*)out;
    const int st = gridDim.x * blockDim.x;
    for (int i = blockIdx.x * blockDim.x + threadIdx.x; i < n4; i += st) {
        float4 v = o4[i];
        v.x = v.x > 0.f ? v.x * invZ : 0.f;
        v.y = v.y > 0.f ? v.y * invZ : 0.f;
        v.z = v.z > 0.f ? v.z * invZ : 0.f;
        v.w = v.w > 0.f ? v.w * invZ : 0.f;
        o4[i] = v;
    }
}

// ---------------------------------------------------------------------------
// Launch: memset(out)+initZ on side stream ∥ build_y; join; edge; finalize.
// ---------------------------------------------------------------------------
extern "C" void kernel_launch(void* const* d_in, const int* in_sizes, int n_in,
                              void* d_out, int out_size)
{
    const int*   uidx = (const int*)d_in[0];
    const int*   iidx = (const int*)d_in[1];
    const int*   ei   = (const int*)d_in[2];
    const float* ut   = (const float*)d_in[5];
    const float* et   = (const float*)d_in[6];
    const float* W    = (const float*)d_in[7];
    float* out = (float*)d_out;
    const int E = in_sizes[2] / 2;

    static cudaStream_t s2 = nullptr;
    static cudaEvent_t ev_fork = nullptr, ev_join = nullptr;
    if (s2 == nullptr) {
        cudaStreamCreateWithFlags(&s2, cudaStreamNonBlocking);
        cudaEventCreateWithFlags(&ev_fork, cudaEventDisableTiming);
        cudaEventCreateWithFlags(&ev_join, cudaEventDisableTiming);
    }

    cudaEventRecord(ev_fork, 0);
    cudaStreamWaitEvent(s2, ev_fork, 0);
    cudaMemsetAsync(out, 0, (size_t)out_size * sizeof(float), s2);
    init_z_kernel<<<1, 1, 0, s2>>>();
    cudaEventRecord(ev_join, s2);

    build_y_kernel<<<(N_TOT + 127) / 128, 256>>>(uidx, iidx, ut, et, W);

    cudaStreamWaitEvent(0, ev_join, 0);
    edge_kernel<<<1184, 256>>>(ei, E, out);
    finalize_kernel<<<1184, 256>>>(out, out_size);
}